// round 8
// baseline (speedup 1.0000x reference)
#include <cuda_runtime.h>
#include <cuda_bf16.h>
#include <cstdint>

#define NN     50000
#define EE     800000
#define EI     200000
#define SLOPE  0.2f

// ---- scratch layout inside d_out (float offsets) -------------------------------
// d_out = NN*128 + EI*256 = 57,600,000 floats. h lives at [0, 6.4M).
// The edges region [6.4M, 57.6M) is written only by the LAST kernel; its front
// is scratch for everything else:
#define S_FT    6400000u     // 6.4M floats : projected features (per layer)
#define S_H1   12800000u     // 6.4M floats : layer-1 output
#define S_EL   19200000u     // 0.2M
#define S_ER   19400000u     // 0.2M
#define S_OFF  19600000u     // NN+1 ints : CSR row offsets
#define S_CUR  19800000u     // NN   ints : counts -> cursors
#define S_EIDX 20000000u     // EE   ints : src id per CSR slot (ends 20.8M)

// ---------------- packed f32x2 helpers (Blackwell FFMA2) ------------------------
__device__ __forceinline__ unsigned long long pk2(float lo, float hi) {
    unsigned long long r;
    asm("mov.b64 %0, {%1, %2};" : "=l"(r) : "f"(lo), "f"(hi));
    return r;
}
__device__ __forceinline__ void ffma2(unsigned long long& d,
                                      unsigned long long a, unsigned long long b) {
    asm("fma.rn.f32x2 %0, %1, %2, %0;" : "+l"(d) : "l"(a), "l"(b));
}
__device__ __forceinline__ float2 up2(unsigned long long v) {
    float2 f;
    asm("mov.b64 {%0, %1}, %2;" : "=f"(f.x), "=f"(f.y) : "l"(v));
    return f;
}

// =================================================================================
// GEMM: ft = X @ W (N x 128 @ 128 x 128), fused el/er.
// 128 threads, tile 64 rows x 128 cols, micro-tile 8x8 per thread (1 B LDS / FMA),
// row-pair packed FFMA2 accumulators. smem 100,352 B -> 2 CTAs/SM.
// =================================================================================
#define XPAD 68
__global__ void __launch_bounds__(128, 2)
gat_gemm_kernel(const float* __restrict__ X, const float* __restrict__ W,
                const float* __restrict__ al, const float* __restrict__ ar,
                float* __restrict__ ft, float* __restrict__ el,
                float* __restrict__ er)
{
    extern __shared__ float smem[];
    float* Ws = smem;             // [128][128]
    float* Xs = smem + 16384;     // [128][XPAD]   Xs[k*XPAD + r]

    const int t    = threadIdx.x;
    const int lane = t & 31;
    const int warp = t >> 5;                       // 0..3
    const int tr0  = warp * 16 + (lane >> 4) * 8;  // 8 rows
    const int tc0  = (lane & 15) * 8;              // 8 cols (within one head)
    const int row0 = blockIdx.x * 64;

    {
        const float4* W4 = reinterpret_cast<const float4*>(W);
        float4* Ws4 = reinterpret_cast<float4*>(Ws);
        #pragma unroll
        for (int i = t; i < 4096; i += 128) Ws4[i] = W4[i];
    }
    for (int i = t; i < 64 * 128; i += 128) {
        int r = i >> 7, k = i & 127;
        int row = row0 + r;
        Xs[k * XPAD + r] = (row < NN) ? X[(size_t)row * 128 + k] : 0.f;
    }
    __syncthreads();

    // acc[rp][c]: row pair (2rp, 2rp+1) of column tc0+c
    unsigned long long acc[4][8];
    #pragma unroll
    for (int rp = 0; rp < 4; rp++)
        #pragma unroll
        for (int c = 0; c < 8; c++) acc[rp][c] = 0ull;

    #pragma unroll 2
    for (int k = 0; k < 128; k++) {
        float4 xa = *reinterpret_cast<const float4*>(&Xs[k * XPAD + tr0]);
        float4 xb = *reinterpret_cast<const float4*>(&Xs[k * XPAD + tr0 + 4]);
        float4 wa = *reinterpret_cast<const float4*>(&Ws[k * 128 + tc0]);
        float4 wb = *reinterpret_cast<const float4*>(&Ws[k * 128 + tc0 + 4]);
        unsigned long long xp[4] = {pk2(xa.x, xa.y), pk2(xa.z, xa.w),
                                    pk2(xb.x, xb.y), pk2(xb.z, xb.w)};
        unsigned long long ww[8] = {pk2(wa.x, wa.x), pk2(wa.y, wa.y),
                                    pk2(wa.z, wa.z), pk2(wa.w, wa.w),
                                    pk2(wb.x, wb.x), pk2(wb.y, wb.y),
                                    pk2(wb.z, wb.z), pk2(wb.w, wb.w)};
        #pragma unroll
        for (int rp = 0; rp < 4; rp++)
            #pragma unroll
            for (int c = 0; c < 8; c++)
                ffma2(acc[rp][c], xp[rp], ww[c]);
    }

    // al/ar are [H][D] = 128 contiguous floats; col index == flat index.
    float alv[8], arv[8];
    #pragma unroll
    for (int c = 0; c < 8; c++) { alv[c] = al[tc0 + c]; arv[c] = ar[tc0 + c]; }
    const int head = (lane & 15) >> 2;   // tc0>>5

    #pragma unroll
    for (int r = 0; r < 8; r++) {
        int rp = r >> 1, hl = r & 1;
        float v[8];
        #pragma unroll
        for (int c = 0; c < 8; c++) {
            float2 p = up2(acc[rp][c]);
            v[c] = hl ? p.y : p.x;
        }
        int row = row0 + tr0 + r;
        float pe = 0.f, pr = 0.f;
        #pragma unroll
        for (int c = 0; c < 8; c++) { pe += v[c] * alv[c]; pr += v[c] * arv[c]; }
        // reduce over the 4 lanes covering this head (lanes base+4h+0..3)
        pe += __shfl_down_sync(0xffffffffu, pe, 2, 4);
        pe += __shfl_down_sync(0xffffffffu, pe, 1, 4);
        pr += __shfl_down_sync(0xffffffffu, pr, 2, 4);
        pr += __shfl_down_sync(0xffffffffu, pr, 1, 4);
        if (row < NN) {
            *reinterpret_cast<float4*>(&ft[(size_t)row * 128 + tc0]) =
                make_float4(v[0], v[1], v[2], v[3]);
            *reinterpret_cast<float4*>(&ft[(size_t)row * 128 + tc0 + 4]) =
                make_float4(v[4], v[5], v[6], v[7]);
            if ((lane & 3) == 0) {
                el[(size_t)row * 4 + head] = pe;
                er[(size_t)row * 4 + head] = pr;
            }
        }
    }
}

// =================================================================================
// CSR build (once per call; reused by both layers — same graph)
// =================================================================================
__global__ void hist_kernel(const int* __restrict__ dst, int* __restrict__ cnt)
{
    int e = blockIdx.x * blockDim.x + threadIdx.x;
    if (e < EE) atomicAdd(&cnt[dst[e]], 1);
}

__global__ void __launch_bounds__(1024, 1)
scan_kernel(int* __restrict__ cntcur, int* __restrict__ off)
{
    __shared__ int ssum[1024];
    const int t = threadIdx.x;
    const int C = (NN + 1023) / 1024;
    int lo = t * C, hi = min(lo + C, NN);
    int s = 0;
    for (int i = lo; i < hi; i++) s += cntcur[i];
    ssum[t] = s;
    __syncthreads();
    for (int d = 1; d < 1024; d <<= 1) {
        int v = (t >= d) ? ssum[t - d] : 0;
        __syncthreads();
        ssum[t] += v;
        __syncthreads();
    }
    int run = (t > 0) ? ssum[t - 1] : 0;
    for (int i = lo; i < hi; i++) {
        int c = cntcur[i];
        off[i] = run;
        cntcur[i] = run;        // becomes scatter cursor
        run += c;
    }
    if (t == 1023) off[NN] = ssum[1023];
}

__global__ void scatter_kernel(const int* __restrict__ src, const int* __restrict__ dst,
                               int* __restrict__ cur, int* __restrict__ eidx)
{
    int e = blockIdx.x * blockDim.x + threadIdx.x;
    if (e >= EE) return;
    int pos = atomicAdd(&cur[dst[e]], 1);
    eidx[pos] = src[e];
}

// =================================================================================
// Gather aggregation + fused normalize + ELU. One warp per dst node, unrolled x4
// to expose MLP on the ft gathers (L2-latency was the R7 bottleneck).
// =================================================================================
__device__ __forceinline__ float elu1(float x) { return (x > 0.f) ? x : expm1f(x); }

__device__ __forceinline__ float att1(float els, float erv) {
    float v = els + erv;
    v = (v > 0.f) ? v : SLOPE * v;
    return __expf(v);
}

__global__ void __launch_bounds__(256, 8)
gat_aggregate_kernel(const int* __restrict__ off, const int* __restrict__ eidx,
                     const float* __restrict__ ft, const float* __restrict__ el,
                     const float* __restrict__ er, float* __restrict__ out)
{
    int d = (blockIdx.x * blockDim.x + threadIdx.x) >> 5;
    if (d >= NN) return;
    int lane = threadIdx.x & 31;
    int hsel = lane >> 3;   // head of this lane's float4

    float erv = (lane < 4) ? er[(size_t)d * 4 + lane] : 0.f;

    int p0 = off[d], p1 = off[d + 1];
    float4 acc = make_float4(0.f, 0.f, 0.f, 0.f);
    float den = 0.f;
    const float4* ft4 = reinterpret_cast<const float4*>(ft);

    int p = p0;
    for (; p + 4 <= p1; p += 4) {
        int s0 = __ldg(&eidx[p]);
        int s1 = __ldg(&eidx[p + 1]);
        int s2 = __ldg(&eidx[p + 2]);
        int s3 = __ldg(&eidx[p + 3]);
        float4 f0 = ft4[(size_t)s0 * 32 + lane];
        float4 f1 = ft4[(size_t)s1 * 32 + lane];
        float4 f2 = ft4[(size_t)s2 * 32 + lane];
        float4 f3 = ft4[(size_t)s3 * 32 + lane];
        float a0 = 0.f, a1 = 0.f, a2 = 0.f, a3 = 0.f;
        if (lane < 4) {
            a0 = att1(el[(size_t)s0 * 4 + lane], erv);
            a1 = att1(el[(size_t)s1 * 4 + lane], erv);
            a2 = att1(el[(size_t)s2 * 4 + lane], erv);
            a3 = att1(el[(size_t)s3 * 4 + lane], erv);
            den += (a0 + a1) + (a2 + a3);
        }
        float h0 = __shfl_sync(0xffffffffu, a0, hsel);
        float h1 = __shfl_sync(0xffffffffu, a1, hsel);
        float h2 = __shfl_sync(0xffffffffu, a2, hsel);
        float h3 = __shfl_sync(0xffffffffu, a3, hsel);
        acc.x += h0 * f0.x + h1 * f1.x + h2 * f2.x + h3 * f3.x;
        acc.y += h0 * f0.y + h1 * f1.y + h2 * f2.y + h3 * f3.y;
        acc.z += h0 * f0.z + h1 * f1.z + h2 * f2.z + h3 * f3.z;
        acc.w += h0 * f0.w + h1 * f1.w + h2 * f2.w + h3 * f3.w;
    }
    for (; p < p1; ++p) {
        int s = __ldg(&eidx[p]);
        float4 f = ft4[(size_t)s * 32 + lane];
        float a = 0.f;
        if (lane < 4) {
            a = att1(el[(size_t)s * 4 + lane], erv);
            den += a;
        }
        float ah = __shfl_sync(0xffffffffu, a, hsel);
        acc.x += ah * f.x; acc.y += ah * f.y;
        acc.z += ah * f.z; acc.w += ah * f.w;
    }

    float inv  = 1.0f / fmaxf(den, 1e-9f);
    float invh = __shfl_sync(0xffffffffu, inv, hsel);
    float4 r;
    r.x = elu1(acc.x * invh);
    r.y = elu1(acc.y * invh);
    r.z = elu1(acc.z * invh);
    r.w = elu1(acc.w * invh);
    reinterpret_cast<float4*>(out)[(size_t)d * 32 + lane] = r;
}

// =================================================================================
// Edge features: out[p, h*64 + 0..31] = hf[i0,h,:], [32..63] = hf[i1,h,:]
// =================================================================================
__global__ void gat_edgefeat_kernel(const float* __restrict__ hf,
                                    const int* __restrict__ ind0,
                                    const int* __restrict__ ind1,
                                    float* __restrict__ out)
{
    int idx = blockIdx.x * blockDim.x + threadIdx.x;
    if (idx >= EI * 64) return;
    int p = idx >> 6;
    int q = idx & 63;
    int h = q >> 4;
    int w = q & 15;
    int node = (w < 8) ? __ldg(&ind0[p]) : __ldg(&ind1[p]);
    float4 v = reinterpret_cast<const float4*>(hf)[(size_t)node * 32 + h * 8 + (w & 7)];
    reinterpret_cast<float4*>(out)[(size_t)p * 64 + q] = v;
}

// =================================================================================
// Launch
// =================================================================================
extern "C" void kernel_launch(void* const* d_in, const int* in_sizes, int n_in,
                              void* d_out, int out_size)
{
    const float* x      = (const float*)d_in[0];
    const int*   src    = (const int*)  d_in[1];
    const int*   dst    = (const int*)  d_in[2];
    const int*   indics = (const int*)  d_in[3];
    const float* W0     = (const float*)d_in[4];
    const float* al0    = (const float*)d_in[5];
    const float* ar0    = (const float*)d_in[6];
    const float* W1     = (const float*)d_in[7];
    const float* al1    = (const float*)d_in[8];
    const float* ar1    = (const float*)d_in[9];

    float* o     = (float*)d_out;
    float* h_out = o;                      // [N, 128]
    float* edges = o + (size_t)NN * 128;   // [E_IND, 256] (written LAST)

    float* ft  = o + S_FT;
    float* h1  = o + S_H1;
    float* el  = o + S_EL;
    float* er  = o + S_ER;
    int*   off = (int*)(o + S_OFF);
    int*   cur = (int*)(o + S_CUR);
    int*   eid = (int*)(o + S_EIDX);

    const int gemm_smem = (16384 + 128 * XPAD) * 4;    // 100,352 B -> 2 CTAs/SM
    static int attr_done = 0;
    if (!attr_done) {
        cudaFuncSetAttribute(gat_gemm_kernel,
                             cudaFuncAttributeMaxDynamicSharedMemorySize, gemm_smem);
        attr_done = 1;
    }

    const int gemm_grid = (NN + 63) / 64;              // 782
    const int edge_grid = (EE + 255) / 256;
    const int agg_grid  = (NN * 32 + 255) / 256;
    const int ef_grid   = (EI * 64 + 255) / 256;

    // ---- CSR build ----
    cudaMemsetAsync(cur, 0, NN * sizeof(int));
    hist_kernel<<<edge_grid, 256>>>(dst, cur);
    scan_kernel<<<1, 1024>>>(cur, off);
    scatter_kernel<<<edge_grid, 256>>>(src, dst, cur, eid);

    // ---- layer 1 ----
    gat_gemm_kernel<<<gemm_grid, 128, gemm_smem>>>(x, W0, al0, ar0, ft, el, er);
    gat_aggregate_kernel<<<agg_grid, 256>>>(off, eid, ft, el, er, h1);

    // ---- layer 2 ----
    gat_gemm_kernel<<<gemm_grid, 128, gemm_smem>>>(h1, W1, al1, ar1, ft, el, er);
    gat_aggregate_kernel<<<agg_grid, 256>>>(off, eid, ft, el, er, h_out);

    // ---- edge features (overwrites scratch region last) ----
    gat_edgefeat_kernel<<<ef_grid, 256>>>(h_out, indics, indics + EI, edges);
}

// round 9
// speedup vs baseline: 1.1369x; 1.1369x over previous
#include <cuda_runtime.h>
#include <cuda_bf16.h>
#include <cstdint>

#define NN     50000
#define EE     800000
#define EI     200000
#define SLOPE  0.2f

// ---- scratch layout inside d_out (float offsets) -------------------------------
// d_out = NN*128 + EI*256 = 57,600,000 floats. h lives at [0, 6.4M).
// The edges region [6.4M, 57.6M) is written only by the LAST kernel; its front
// is scratch for everything else:
#define S_FT    6400000u     // 6.4M floats : projected features (per layer)
#define S_H1   12800000u     // 6.4M floats : layer-1 output
#define S_EL   19200000u     // 0.2M
#define S_ER   19400000u     // 0.2M
#define S_OFF  19600000u     // NN+1 ints : CSR row offsets
#define S_CUR  19800000u     // NN   ints : counts -> cursors
#define S_EIDX 20000000u     // EE   ints : src id per CSR slot (ends 20.8M)

// ---------------- packed f32x2 helpers (Blackwell FFMA2) ------------------------
__device__ __forceinline__ unsigned long long pk2(float lo, float hi) {
    unsigned long long r;
    asm("mov.b64 %0, {%1, %2};" : "=l"(r) : "f"(lo), "f"(hi));
    return r;
}
__device__ __forceinline__ void ffma2(unsigned long long& d,
                                      unsigned long long a, unsigned long long b) {
    asm("fma.rn.f32x2 %0, %1, %2, %0;" : "+l"(d) : "l"(a), "l"(b));
}
__device__ __forceinline__ float2 up2(unsigned long long v) {
    float2 f;
    asm("mov.b64 {%0, %1}, %2;" : "=f"(f.x), "=f"(f.y) : "l"(v));
    return f;
}

// =================================================================================
// GEMM (R7 version — measured 57.7us): ft = X @ W, fused el/er.
// 512 threads, 128-row tile, micro-tile 8x4 per thread, packed FFMA2.
// =================================================================================
#define XPAD 132
__global__ void __launch_bounds__(512, 1)
gat_gemm_kernel(const float* __restrict__ X, const float* __restrict__ W,
                const float* __restrict__ al, const float* __restrict__ ar,
                float* __restrict__ ft, float* __restrict__ el,
                float* __restrict__ er)
{
    extern __shared__ float smem[];
    float* Ws = smem;             // [128][128]
    float* Xs = smem + 16384;     // [128][XPAD]  Xs[k*XPAD + r]

    const int t    = threadIdx.x;
    const int lane = t & 31;
    const int warp = t >> 5;      // 0..15
    const int c0   = lane * 4;
    const int r0   = warp * 8;
    const int row0 = blockIdx.x * 128;

    {
        const float4* W4 = reinterpret_cast<const float4*>(W);
        float4* Ws4 = reinterpret_cast<float4*>(Ws);
        #pragma unroll
        for (int i = t; i < 4096; i += 512) Ws4[i] = W4[i];
    }
    const float4 alv = reinterpret_cast<const float4*>(al)[lane];
    const float4 arv = reinterpret_cast<const float4*>(ar)[lane];

    for (int i = t; i < 128 * 128; i += 512) {
        int r = i >> 7, k = i & 127;
        int row = row0 + r;
        Xs[k * XPAD + r] = (row < NN) ? X[(size_t)row * 128 + k] : 0.f;
    }
    __syncthreads();

    unsigned long long acc[4][4];
    #pragma unroll
    for (int rp = 0; rp < 4; rp++)
        #pragma unroll
        for (int c = 0; c < 4; c++) acc[rp][c] = 0ull;

    #pragma unroll 4
    for (int k = 0; k < 128; k++) {
        float4 w  = *reinterpret_cast<const float4*>(&Ws[k * 128 + c0]);
        float4 x0 = *reinterpret_cast<const float4*>(&Xs[k * XPAD + r0]);
        float4 x1 = *reinterpret_cast<const float4*>(&Xs[k * XPAD + r0 + 4]);
        unsigned long long ww[4] = {pk2(w.x, w.x), pk2(w.y, w.y),
                                    pk2(w.z, w.z), pk2(w.w, w.w)};
        unsigned long long xp[4] = {pk2(x0.x, x0.y), pk2(x0.z, x0.w),
                                    pk2(x1.x, x1.y), pk2(x1.z, x1.w)};
        #pragma unroll
        for (int rp = 0; rp < 4; rp++) {
            ffma2(acc[rp][0], xp[rp], ww[0]);
            ffma2(acc[rp][1], xp[rp], ww[1]);
            ffma2(acc[rp][2], xp[rp], ww[2]);
            ffma2(acc[rp][3], xp[rp], ww[3]);
        }
    }

    #pragma unroll
    for (int r = 0; r < 8; r++) {
        int rp = r >> 1, hl = r & 1;
        float v0 = hl ? up2(acc[rp][0]).y : up2(acc[rp][0]).x;
        float v1 = hl ? up2(acc[rp][1]).y : up2(acc[rp][1]).x;
        float v2 = hl ? up2(acc[rp][2]).y : up2(acc[rp][2]).x;
        float v3 = hl ? up2(acc[rp][3]).y : up2(acc[rp][3]).x;
        int row = row0 + r0 + r;
        float pe = v0*alv.x + v1*alv.y + v2*alv.z + v3*alv.w;
        float pr = v0*arv.x + v1*arv.y + v2*arv.z + v3*arv.w;
        pe += __shfl_down_sync(0xffffffffu, pe, 4, 8);
        pe += __shfl_down_sync(0xffffffffu, pe, 2, 8);
        pe += __shfl_down_sync(0xffffffffu, pe, 1, 8);
        pr += __shfl_down_sync(0xffffffffu, pr, 4, 8);
        pr += __shfl_down_sync(0xffffffffu, pr, 2, 8);
        pr += __shfl_down_sync(0xffffffffu, pr, 1, 8);
        if (row < NN) {
            *reinterpret_cast<float4*>(&ft[(size_t)row * 128 + c0]) =
                make_float4(v0, v1, v2, v3);
            if ((lane & 7) == 0) {
                int h = lane >> 3;
                el[(size_t)row * 4 + h] = pe;
                er[(size_t)row * 4 + h] = pr;
            }
        }
    }
}

// =================================================================================
// CSR build (once per call; reused by both layers — same graph)
// =================================================================================
__global__ void hist_kernel(const int* __restrict__ dst, int* __restrict__ cnt)
{
    int e = blockIdx.x * blockDim.x + threadIdx.x;
    if (e < EE) atomicAdd(&cnt[dst[e]], 1);
}

__global__ void __launch_bounds__(1024, 1)
scan_kernel(int* __restrict__ cntcur, int* __restrict__ off)
{
    __shared__ int ssum[1024];
    const int t = threadIdx.x;
    const int C = (NN + 1023) / 1024;
    int lo = t * C, hi = min(lo + C, NN);
    int s = 0;
    for (int i = lo; i < hi; i++) s += cntcur[i];
    ssum[t] = s;
    __syncthreads();
    for (int d = 1; d < 1024; d <<= 1) {
        int v = (t >= d) ? ssum[t - d] : 0;
        __syncthreads();
        ssum[t] += v;
        __syncthreads();
    }
    int run = (t > 0) ? ssum[t - 1] : 0;
    for (int i = lo; i < hi; i++) {
        int c = cntcur[i];
        off[i] = run;
        cntcur[i] = run;        // becomes scatter cursor
        run += c;
    }
    if (t == 1023) off[NN] = ssum[1023];
}

__global__ void scatter_kernel(const int* __restrict__ src, const int* __restrict__ dst,
                               int* __restrict__ cur, int* __restrict__ eidx)
{
    int e = blockIdx.x * blockDim.x + threadIdx.x;
    if (e >= EE) return;
    int pos = atomicAdd(&cur[dst[e]], 1);
    eidx[pos] = src[e];
}

// =================================================================================
// Gather aggregation + fused normalize + ELU. One warp per dst node.
// x4 unroll for ft-gather MLP; el gathers spread over 16 lanes (lane = edge*4+head).
// launch_bounds(256,4): 64-reg budget so the unroll does NOT spill (R8 bug).
// =================================================================================
__device__ __forceinline__ float elu1(float x) { return (x > 0.f) ? x : expm1f(x); }

__device__ __forceinline__ float att1(float els, float erv) {
    float v = els + erv;
    v = (v > 0.f) ? v : SLOPE * v;
    return __expf(v);
}

__global__ void __launch_bounds__(256, 4)
gat_aggregate_kernel(const int* __restrict__ off, const int* __restrict__ eidx,
                     const float* __restrict__ ft, const float* __restrict__ el,
                     const float* __restrict__ er, float* __restrict__ out)
{
    int d = (blockIdx.x * blockDim.x + threadIdx.x) >> 5;
    if (d >= NN) return;
    const int lane = threadIdx.x & 31;
    const int hsel = lane >> 3;            // head of this lane's float4 chunk

    // lanes 0..15: er for head (lane&3)
    float er16 = (lane < 16) ? er[(size_t)d * 4 + (lane & 3)] : 0.f;

    int p0 = off[d], p1 = off[d + 1];
    float4 acc = make_float4(0.f, 0.f, 0.f, 0.f);
    float den16 = 0.f;                     // lanes 0..15: partial denom, head lane&3
    const float4* ft4 = reinterpret_cast<const float4*>(ft);

    int p = p0;
    for (; p + 4 <= p1; p += 4) {
        int s0 = __ldg(&eidx[p]);
        int s1 = __ldg(&eidx[p + 1]);
        int s2 = __ldg(&eidx[p + 2]);
        int s3 = __ldg(&eidx[p + 3]);
        float4 f0 = ft4[(size_t)s0 * 32 + lane];
        float4 f1 = ft4[(size_t)s1 * 32 + lane];
        float4 f2 = ft4[(size_t)s2 * 32 + lane];
        float4 f3 = ft4[(size_t)s3 * 32 + lane];
        float a = 0.f;
        if (lane < 16) {                   // lane = e*4 + h
            int q = lane >> 2;
            int se = s0;
            if (q == 1) se = s1;
            else if (q == 2) se = s2;
            else if (q == 3) se = s3;
            a = att1(__ldg(&el[(size_t)se * 4 + (lane & 3)]), er16);
            den16 += a;
        }
        float h0 = __shfl_sync(0xffffffffu, a, hsel);
        float h1 = __shfl_sync(0xffffffffu, a, 4 + hsel);
        float h2 = __shfl_sync(0xffffffffu, a, 8 + hsel);
        float h3 = __shfl_sync(0xffffffffu, a, 12 + hsel);
        acc.x += h0 * f0.x + h1 * f1.x + h2 * f2.x + h3 * f3.x;
        acc.y += h0 * f0.y + h1 * f1.y + h2 * f2.y + h3 * f3.y;
        acc.z += h0 * f0.z + h1 * f1.z + h2 * f2.z + h3 * f3.z;
        acc.w += h0 * f0.w + h1 * f1.w + h2 * f2.w + h3 * f3.w;
    }
    for (; p < p1; ++p) {                  // tail (<4 edges)
        int s = __ldg(&eidx[p]);
        float4 f = ft4[(size_t)s * 32 + lane];
        float a = 0.f;
        if (lane < 4) {                    // lane&3 == lane: er16 consistent
            a = att1(__ldg(&el[(size_t)s * 4 + lane]), er16);
            den16 += a;
        }
        float ah = __shfl_sync(0xffffffffu, a, hsel);
        acc.x += ah * f.x; acc.y += ah * f.y;
        acc.z += ah * f.z; acc.w += ah * f.w;
    }

    // reduce den over the 4 lane-groups: lanes 0..3 end with den[h]
    den16 += __shfl_down_sync(0xffffffffu, den16, 8);
    den16 += __shfl_down_sync(0xffffffffu, den16, 4);
    float inv  = 1.0f / fmaxf(den16, 1e-9f);
    float invh = __shfl_sync(0xffffffffu, inv, hsel);
    float4 r;
    r.x = elu1(acc.x * invh);
    r.y = elu1(acc.y * invh);
    r.z = elu1(acc.z * invh);
    r.w = elu1(acc.w * invh);
    reinterpret_cast<float4*>(out)[(size_t)d * 32 + lane] = r;
}

// =================================================================================
// Edge features: out[p, h*64 + 0..31] = hf[i0,h,:], [32..63] = hf[i1,h,:]
// =================================================================================
__global__ void gat_edgefeat_kernel(const float* __restrict__ hf,
                                    const int* __restrict__ ind0,
                                    const int* __restrict__ ind1,
                                    float* __restrict__ out)
{
    int idx = blockIdx.x * blockDim.x + threadIdx.x;
    if (idx >= EI * 64) return;
    int p = idx >> 6;
    int q = idx & 63;
    int h = q >> 4;
    int w = q & 15;
    int node = (w < 8) ? __ldg(&ind0[p]) : __ldg(&ind1[p]);
    float4 v = reinterpret_cast<const float4*>(hf)[(size_t)node * 32 + h * 8 + (w & 7)];
    reinterpret_cast<float4*>(out)[(size_t)p * 64 + q] = v;
}

// =================================================================================
// Launch
// =================================================================================
extern "C" void kernel_launch(void* const* d_in, const int* in_sizes, int n_in,
                              void* d_out, int out_size)
{
    const float* x      = (const float*)d_in[0];
    const int*   src    = (const int*)  d_in[1];
    const int*   dst    = (const int*)  d_in[2];
    const int*   indics = (const int*)  d_in[3];
    const float* W0     = (const float*)d_in[4];
    const float* al0    = (const float*)d_in[5];
    const float* ar0    = (const float*)d_in[6];
    const float* W1     = (const float*)d_in[7];
    const float* al1    = (const float*)d_in[8];
    const float* ar1    = (const float*)d_in[9];

    float* o     = (float*)d_out;
    float* h_out = o;                      // [N, 128]
    float* edges = o + (size_t)NN * 128;   // [E_IND, 256] (written LAST)

    float* ft  = o + S_FT;
    float* h1  = o + S_H1;
    float* el  = o + S_EL;
    float* er  = o + S_ER;
    int*   off = (int*)(o + S_OFF);
    int*   cur = (int*)(o + S_CUR);
    int*   eid = (int*)(o + S_EIDX);

    const int gemm_smem = (16384 + 128 * XPAD) * 4;    // 133,120 B
    static int attr_done = 0;
    if (!attr_done) {
        cudaFuncSetAttribute(gat_gemm_kernel,
                             cudaFuncAttributeMaxDynamicSharedMemorySize, gemm_smem);
        attr_done = 1;
    }

    const int gemm_grid = (NN + 127) / 128;            // 391
    const int edge_grid = (EE + 255) / 256;
    const int agg_grid  = (NN * 32 + 255) / 256;
    const int ef_grid   = (EI * 64 + 255) / 256;

    // ---- CSR build ----
    cudaMemsetAsync(cur, 0, NN * sizeof(int));
    hist_kernel<<<edge_grid, 256>>>(dst, cur);
    scan_kernel<<<1, 1024>>>(cur, off);
    scatter_kernel<<<edge_grid, 256>>>(src, dst, cur, eid);

    // ---- layer 1 ----
    gat_gemm_kernel<<<gemm_grid, 512, gemm_smem>>>(x, W0, al0, ar0, ft, el, er);
    gat_aggregate_kernel<<<agg_grid, 256>>>(off, eid, ft, el, er, h1);

    // ---- layer 2 ----
    gat_gemm_kernel<<<gemm_grid, 512, gemm_smem>>>(h1, W1, al1, ar1, ft, el, er);
    gat_aggregate_kernel<<<agg_grid, 256>>>(off, eid, ft, el, er, h_out);

    // ---- edge features (overwrites scratch region last) ----
    gat_edgefeat_kernel<<<ef_grid, 256>>>(h_out, indics, indics + EI, edges);
}